// round 9
// baseline (speedup 1.0000x reference)
#include <cuda_runtime.h>
#include <math.h>

#define NN 6000
#define EE 120000
#define DD 128
#define DE 128
#define HH 4
#define LL 2
#define CC 384      // 2*DD + DE
#define HD 512      // HH*DD
#define D4 512      // 4*DD

// ---------------- scratch (device globals; no allocation) ----------------
__device__ float    g_t1[(size_t)EE * DD];
__device__ float    g_t2[(size_t)EE * DD];
__device__ float    g_nupd[(size_t)EE * DD];
__device__ float    g_eattr[(size_t)EE * DE];
__device__ float    g_scores[(size_t)EE * HH];
__device__ float    g_att[(size_t)EE * HH];
__device__ unsigned g_smaxu[NN * HH];
__device__ float    g_norm[NN * HH];
__device__ float    g_agg[(size_t)NN * HD];
__device__ float    g_nodes[NN * DD];
__device__ float    g_upd[NN * DD];
__device__ float    g_dense[(size_t)NN * D4];
__device__ float    g_dense2[NN * DD];
__device__ float    g_Wa[(size_t)LL * CC * HD];    // attention W packed [l][c][h*D+d]
__device__ float    g_WU1[(size_t)LL * DD * 1280]; // [Wa_src|Wa_snk|nW1_src|nW1_snk]
__device__ float    g_WU2[(size_t)LL * DD * 256];  // [eW1_src|eW1_snk]
__device__ float    g_U1[(size_t)NN * 1280];       // per-node partials (attn + nmlp1)
__device__ float    g_U2[(size_t)NN * 256];        // per-node partials (emlp1)
__device__ float    g_zero[1536];                  // zero bias (never written)

// ---------------- helpers ----------------
__device__ __forceinline__ float gelu_f(float x) {
    return 0.5f * x * (1.0f + erff(x * 0.70710678118654752440f));
}
__device__ __forceinline__ unsigned f2u(float f) {
    unsigned u = __float_as_uint(f);
    return (u & 0x80000000u) ? ~u : (u | 0x80000000u);
}
__device__ __forceinline__ float u2f(unsigned u) {
    return (u & 0x80000000u) ? __uint_as_float(u & 0x7fffffffu) : __uint_as_float(~u);
}
__device__ __forceinline__ float tf32f(float x) {
    unsigned r;
    asm("cvt.rna.tf32.f32 %0, %1;" : "=r"(r) : "f"(x));
    return __uint_as_float(r);
}
__device__ __forceinline__ float4 tf32f4(float4 v) {
    return make_float4(tf32f(v.x), tf32f(v.y), tf32f(v.z), tf32f(v.w));
}
__device__ __forceinline__ void mma_tf32(float* d, const unsigned* a, const unsigned* b) {
    asm volatile(
        "mma.sync.aligned.m16n8k8.row.col.f32.tf32.tf32.f32 "
        "{%0,%1,%2,%3}, {%4,%5,%6,%7}, {%8,%9}, {%0,%1,%2,%3};"
        : "+f"(d[0]), "+f"(d[1]), "+f"(d[2]), "+f"(d[3])
        : "r"(a[0]), "r"(a[1]), "r"(a[2]), "r"(a[3]), "r"(b[0]), "r"(b[1]));
}

// ---------------- small kernels ----------------
__global__ void pack_wa(const float* __restrict__ aW) {
    int i = blockIdx.x * blockDim.x + threadIdx.x;
    if (i >= LL * HH * CC * DD) return;
    int d = i % DD;
    int c = (i / DD) % CC;
    int h = (i / (DD * CC)) % HH;
    int l = i / (DD * CC * HH);
    g_Wa[((size_t)l * CC + c) * HD + h * DD + d] = aW[i];
}

__global__ void pack_u1(const float* __restrict__ aW, const float* __restrict__ nW1) {
    int i = blockIdx.x * blockDim.x + threadIdx.x;
    if (i >= LL * DD * 1280) return;
    int j = i % 1280;
    int k = (i / 1280) % DD;
    int l = i / (1280 * DD);
    float v;
    if (j < 1024) {
        int c = (j < 512) ? k : (128 + k);
        int jj = j & 511;
        int h = jj >> 7, d = jj & 127;
        v = aW[(((size_t)l * HH + h) * CC + c) * DD + d];
    } else {
        int c = (j < 1152) ? k : (128 + k);
        int d = (j - 1024) & 127;
        v = nW1[((size_t)l * CC + c) * DD + d];
    }
    g_WU1[i] = v;
}

__global__ void pack_u2(const float* __restrict__ eW1) {
    int i = blockIdx.x * blockDim.x + threadIdx.x;
    if (i >= LL * DD * 256) return;
    int j = i % 256;
    int k = (i / 256) % DD;
    int l = i / (256 * DD);
    int c = (j < 128) ? k : (128 + k);
    g_WU2[i] = eW1[((size_t)l * CC + c) * DE + (j & 127)];
}

__global__ void node_embed(const int* __restrict__ seq, const float* __restrict__ emb) {
    int i = blockIdx.x * blockDim.x + threadIdx.x;
    if (i < NN * DD) g_nodes[i] = emb[seq[i / DD] * DD + (i % DD)];
}

__global__ void edge_init(const float* __restrict__ dist,
                          const float* __restrict__ W, const float* __restrict__ b) {
    int e = blockIdx.x;
    int t = threadIdx.x;
    __shared__ float rbf[16];
    if (t < 16) {
        float mu = 2.0f + (20.0f / 15.0f) * (float)t;
        float z = (dist[e] - mu) * (1.0f / 1.25f);
        rbf[t] = expf(-z * z) + 1e-8f;
    }
    __syncthreads();
    float acc = b[t];
#pragma unroll
    for (int k = 0; k < 16; k++) acc = fmaf(rbf[k], W[k * DE + t], acc);
    g_eattr[(size_t)e * DE + t] = acc;
}

// zero agg + softmax max/norm buffers in one launch
__global__ void zero_buffers() {
    int i = blockIdx.x * blockDim.x + threadIdx.x;
    if (i < NN * HD) g_agg[i] = 0.0f;
    if (i < NN * HH) { g_smaxu[i] = 0u; g_norm[i] = 0.0f; }
}

__global__ void smax_atomic(const int* __restrict__ snk) {
    int i = blockIdx.x * blockDim.x + threadIdx.x;
    if (i >= EE * HH) return;
    int e = i / HH, h = i % HH;
    atomicMax(&g_smaxu[snk[e] * HH + h], f2u(g_scores[i]));
}

__global__ void att_kernel(const int* __restrict__ snk) {
    int i = blockIdx.x * blockDim.x + threadIdx.x;
    if (i >= EE * HH) return;
    int e = i / HH, h = i % HH;
    int s = snk[e];
    float a = expf(g_scores[i] - u2f(g_smaxu[s * HH + h]));
    g_att[i] = a;
    atomicAdd(&g_norm[s * HH + h], a + 1e-12f);
}

__global__ void recip_norm() {
    int i = blockIdx.x * blockDim.x + threadIdx.x;
    if (i < NN * HH) g_norm[i] = 1.0f / g_norm[i];
}

__global__ void aggregate(const int* __restrict__ snk) {
    int i = blockIdx.x * blockDim.x + threadIdx.x;
    if (i >= EE * 32) return;
    int e = i >> 5;
    int d4 = i & 31;
    float4 v = ((const float4*)g_nupd)[(size_t)e * 32 + d4];
    int s = snk[e];
    float4 w = *(const float4*)(g_att + e * 4);
    float4 rn = *(const float4*)(g_norm + s * 4);
    float4* base = (float4*)(g_agg + (size_t)s * HD) + d4;
    float c0 = w.x * rn.x, c1 = w.y * rn.y, c2 = w.z * rn.z, c3 = w.w * rn.w;
    atomicAdd(base,      make_float4(c0 * v.x, c0 * v.y, c0 * v.z, c0 * v.w));
    atomicAdd(base + 32, make_float4(c1 * v.x, c1 * v.y, c1 * v.z, c1 * v.w));
    atomicAdd(base + 64, make_float4(c2 * v.x, c2 * v.y, c2 * v.z, c2 * v.w));
    atomicAdd(base + 96, make_float4(c3 * v.x, c3 * v.y, c3 * v.z, c3 * v.w));
}

// LayerNorm: warp per row, 8 rows per 256-thread block. out = LN(A+R)*g+b.
__global__ void ln_fast(const float* __restrict__ A, const float* __restrict__ R,
                        const float* __restrict__ g, const float* __restrict__ b,
                        float* __restrict__ out, float* __restrict__ out2, int M) {
    int row = blockIdx.x * 8 + (threadIdx.x >> 5);
    if (row >= M) return;
    int lane = threadIdx.x & 31;
    float4 a = *(const float4*)(A + (size_t)row * DD + lane * 4);
    float4 r = *(const float4*)(R + (size_t)row * DD + lane * 4);
    float x0 = a.x + r.x, x1 = a.y + r.y, x2 = a.z + r.z, x3 = a.w + r.w;
    float s = x0 + x1 + x2 + x3;
    float sq = x0 * x0 + x1 * x1 + x2 * x2 + x3 * x3;
#pragma unroll
    for (int o = 16; o > 0; o >>= 1) {
        s  += __shfl_xor_sync(0xffffffffu, s, o);
        sq += __shfl_xor_sync(0xffffffffu, sq, o);
    }
    float mean = s * (1.0f / 128.0f);
    float var = sq * (1.0f / 128.0f) - mean * mean;
    float rstd = rsqrtf(var + 1e-5f);
    float4 gv = *(const float4*)(g + lane * 4);
    float4 bv = *(const float4*)(b + lane * 4);
    float4 o4;
    o4.x = (x0 - mean) * rstd * gv.x + bv.x;
    o4.y = (x1 - mean) * rstd * gv.y + bv.y;
    o4.z = (x2 - mean) * rstd * gv.z + bv.z;
    o4.w = (x3 - mean) * rstd * gv.w + bv.w;
    *(float4*)(out + (size_t)row * DD + lane * 4) = o4;
    if (out2) *(float4*)(out2 + (size_t)row * DD + lane * 4) = o4;
}

// ---------------- tf32 tensor-core GEMM, double-buffered, compile-time K ----------------
// C[M,N] = act(A@B + bias [+ U[src]+U[snk]]). BM=128, BN=128, BK=16, 256 thr,
// warp tile 64x32. N multiple of 128.
// ADDUV: epilogue adds U[src[r]*ldu + offS + c] + U[snk[r]*ldu + offK + c].
// ATTN:  BN==head width; lrelu then dot(aA) reduced to g_scores directly.
template <int ACT, bool ATTN, bool ADDUV, int KK>   // ACT: 0 none, 1 gelu
__global__ void __launch_bounds__(256) gemm_tc(
    const float* __restrict__ A, int lda,
    const float* __restrict__ B, int ldb,
    const float* __restrict__ bias,
    const float* __restrict__ aA, const float* __restrict__ aAb,
    const int* __restrict__ srcI, const int* __restrict__ snkI,
    const float* __restrict__ U, int ldu, int offS, int offK,
    float* __restrict__ C, int ldc, int M) {
    __shared__ float As[2][128][20];
    __shared__ float Bs[2][16][136];
    __shared__ float sred[128][5];
    const int tid = threadIdx.x;
    const int row0 = blockIdx.y * 128, col0 = blockIdx.x * 128;
    const int wid = tid >> 5, lane = tid & 31, g = lane >> 2, tig = lane & 3;
    const int wm0 = (wid >> 2) * 64, wn0 = (wid & 3) * 32;

    const int arow = tid >> 2, acol = (tid & 3) * 4;
    const int ag0 = min(row0 + arow, M - 1);
    const int ag1 = min(row0 + arow + 64, M - 1);
    const int brow = tid >> 5, bcol = (tid & 31) * 4;

    const float* Ap0 = A + (size_t)ag0 * lda + acol;
    const float* Ap1 = A + (size_t)ag1 * lda + acol;
    const float* Bp  = B + (size_t)brow * ldb + col0 + bcol;

    float4 ar0 = *(const float4*)Ap0;
    float4 ar1 = *(const float4*)Ap1;
    float4 br0 = *(const float4*)Bp;
    float4 br1 = *(const float4*)(Bp + (size_t)8 * ldb);
    *(float4*)&As[0][arow][acol]      = tf32f4(ar0);
    *(float4*)&As[0][arow + 64][acol] = tf32f4(ar1);
    *(float4*)&Bs[0][brow][bcol]      = tf32f4(br0);
    *(float4*)&Bs[0][brow + 8][bcol]  = tf32f4(br1);
    __syncthreads();

    float acc[4][4][4] = {};
    int buf = 0;
#pragma unroll 4
    for (int k0 = 0; k0 < KK; k0 += 16, buf ^= 1) {
        const bool more = (k0 + 16) < KK;
        if (more) {
            ar0 = *(const float4*)(Ap0 + k0 + 16);
            ar1 = *(const float4*)(Ap1 + k0 + 16);
            br0 = *(const float4*)(Bp + (size_t)(k0 + 16) * ldb);
            br1 = *(const float4*)(Bp + (size_t)(k0 + 24) * ldb);
        }
#pragma unroll
        for (int ks = 0; ks < 16; ks += 8) {
            unsigned af[4][4], bf[4][2];
#pragma unroll
            for (int mt = 0; mt < 4; mt++) {
                int r = wm0 + mt * 16 + g;
                af[mt][0] = __float_as_uint(As[buf][r][ks + tig]);
                af[mt][1] = __float_as_uint(As[buf][r + 8][ks + tig]);
                af[mt][2] = __float_as_uint(As[buf][r][ks + tig + 4]);
                af[mt][3] = __float_as_uint(As[buf][r + 8][ks + tig + 4]);
            }
#pragma unroll
            for (int nt = 0; nt < 4; nt++) {
                int c = wn0 + nt * 8 + g;
                bf[nt][0] = __float_as_uint(Bs[buf][ks + tig][c]);
                bf[nt][1] = __float_as_uint(Bs[buf][ks + tig + 4][c]);
            }
#pragma unroll
            for (int mt = 0; mt < 4; mt++)
#pragma unroll
                for (int nt = 0; nt < 4; nt++)
                    mma_tf32(acc[mt][nt], af[mt], bf[nt]);
        }
        if (more) {
            *(float4*)&As[buf ^ 1][arow][acol]      = tf32f4(ar0);
            *(float4*)&As[buf ^ 1][arow + 64][acol] = tf32f4(ar1);
            *(float4*)&Bs[buf ^ 1][brow][bcol]      = tf32f4(br0);
            *(float4*)&Bs[buf ^ 1][brow + 8][bcol]  = tf32f4(br1);
        }
        __syncthreads();
    }

#pragma unroll
    for (int mt = 0; mt < 4; mt++) {
#pragma unroll
        for (int i2 = 0; i2 < 2; i2++) {
            int rl = wm0 + mt * 16 + i2 * 8 + g;
            int gr = row0 + rl;
            int grc = min(gr, M - 1);
            int sI = 0, kI = 0;
            if (ADDUV) { sI = srcI[grc]; kI = snkI[grc]; }
            float p = 0.0f;
#pragma unroll
            for (int nt = 0; nt < 4; nt++) {
                int gc = col0 + wn0 + nt * 8 + 2 * tig;
                float2 bb = *(const float2*)&bias[gc];
                float v0 = acc[mt][nt][i2 * 2 + 0] + bb.x;
                float v1 = acc[mt][nt][i2 * 2 + 1] + bb.y;
                if (ADDUV) {
                    float2 us = *(const float2*)&U[(size_t)sI * ldu + offS + gc];
                    float2 uk = *(const float2*)&U[(size_t)kI * ldu + offK + gc];
                    v0 += us.x + uk.x;
                    v1 += us.y + uk.y;
                }
                if (ATTN) {
                    v0 = (v0 > 0.0f) ? v0 : 0.2f * v0;
                    v1 = (v1 > 0.0f) ? v1 : 0.2f * v1;
                    float2 a2 = *(const float2*)&aA[gc];
                    p = fmaf(v0, a2.x, p);
                    p = fmaf(v1, a2.y, p);
                } else {
                    if (ACT == 1) { v0 = gelu_f(v0); v1 = gelu_f(v1); }
                    if (gr < M) *(float2*)&C[(size_t)gr * ldc + gc] = make_float2(v0, v1);
                }
            }
            if (ATTN) {
                p += __shfl_xor_sync(0xffffffffu, p, 1);
                p += __shfl_xor_sync(0xffffffffu, p, 2);
                if (tig == 0) sred[rl][wid & 3] = p;
            }
        }
    }
    if (ATTN) {
        __syncthreads();
        if (tid < 128) {
            int gr = row0 + tid;
            if (gr < M) {
                int head = col0 >> 7;
                g_scores[gr * HH + head] =
                    sred[tid][0] + sred[tid][1] + sred[tid][2] + sred[tid][3] + aAb[head];
            }
        }
    }
}

// ---------------- host ----------------
static inline void* sym(const void* s) {
    void* p = nullptr;
    cudaGetSymbolAddress(&p, s);
    return p;
}

extern "C" void kernel_launch(void* const* d_in, const int* in_sizes, int n_in,
                              void* d_out, int out_size) {
    const int*   seq      = (const int*)d_in[0];
    const int*   eidx     = (const int*)d_in[1];
    const float* dist     = (const float*)d_in[2];
    const float* seq_emb  = (const float*)d_in[3];
    const float* elW      = (const float*)d_in[4];
    const float* elb      = (const float*)d_in[5];
    const float* aW_W     = (const float*)d_in[6];
    const float* aW_b     = (const float*)d_in[7];
    const float* aA_W     = (const float*)d_in[8];
    const float* aA_b     = (const float*)d_in[9];
    const float* nW1 = (const float*)d_in[10]; const float* nb1 = (const float*)d_in[11];
    const float* nW2 = (const float*)d_in[12]; const float* nb2 = (const float*)d_in[13];
    const float* nW3 = (const float*)d_in[14]; const float* nb3 = (const float*)d_in[15];
    const float* dW1 = (const float*)d_in[16]; const float* db1 = (const float*)d_in[17];
    const float* dW2 = (const float*)d_in[18]; const float* db2 = (const float*)d_in[19];
    const float* eW1 = (const float*)d_in[20]; const float* eb1 = (const float*)d_in[21];
    const float* eW2 = (const float*)d_in[22]; const float* eb2 = (const float*)d_in[23];
    const float* eW3 = (const float*)d_in[24]; const float* eb3 = (const float*)d_in[25];
    const float* agW = (const float*)d_in[26]; const float* agb = (const float*)d_in[27];
    const float* n1g = (const float*)d_in[28]; const float* n1b = (const float*)d_in[29];
    const float* eg  = (const float*)d_in[30]; const float* eb  = (const float*)d_in[31];

    const int* srcp = eidx;
    const int* snkp = eidx + EE;

    float* t1     = (float*)sym(g_t1);
    float* t2     = (float*)sym(g_t2);
    float* nupd   = (float*)sym(g_nupd);
    float* agg    = (float*)sym(g_agg);
    float* nodes  = (float*)sym(g_nodes);
    float* upd    = (float*)sym(g_upd);
    float* dense  = (float*)sym(g_dense);
    float* dense2 = (float*)sym(g_dense2);
    float* Wa     = (float*)sym(g_Wa);
    float* WU1    = (float*)sym(g_WU1);
    float* WU2    = (float*)sym(g_WU2);
    float* U1     = (float*)sym(g_U1);
    float* U2     = (float*)sym(g_U2);
    float* zerob  = (float*)sym(g_zero);
    float* eattr  = (float*)sym(g_eattr);

    const int GME = (EE + 127) / 128;
    const int GMN = (NN + 127) / 128;

    {
        pack_wa<<<(LL * HH * CC * DD + 255) / 256, 256>>>(aW_W);
        pack_u1<<<(LL * DD * 1280 + 255) / 256, 256>>>(aW_W, nW1);
        pack_u2<<<(LL * DD * 256 + 255) / 256, 256>>>(eW1);
        node_embed<<<(NN * DD + 255) / 256, 256>>>(seq, seq_emb);
        edge_init<<<EE, 128>>>(dist, elW, elb);
    }

    for (int l = 0; l < LL; l++) {
        const bool last = (l == LL - 1);

        // per-node partials for attn + nmlp1
        gemm_tc<0, false, false, 128><<<dim3(10, GMN), 256>>>(
            nodes, DD, WU1 + (size_t)l * DD * 1280, 1280, zerob, nullptr, nullptr,
            nullptr, nullptr, nullptr, 0, 0, 0, U1, 1280, NN);

        // attention scores: eattr @ Wa_e + U1 gathers, lrelu, dot(aA)
        gemm_tc<0, true, true, 128><<<dim3(4, GME), 256>>>(
            eattr, DE, Wa + ((size_t)l * CC + 256) * HD, HD, aW_b + l * HD,
            aA_W + l * HD, aA_b + l * HH,
            srcp, snkp, U1, 1280, 0, 512, nullptr, 0, EE);

        // nmlp: W1 (edge part + U1 gathers), then W2, W3
        gemm_tc<1, false, true, 128><<<dim3(1, GME), 256>>>(
            eattr, DE, nW1 + ((size_t)l * CC + 256) * DD, DD, nb1 + l * DD,
            nullptr, nullptr, srcp, snkp, U1, 1280, 1024, 1152, t1, DD, EE);
        gemm_tc<1, false, false, 128><<<dim3(1, GME), 256>>>(
            t1, DD, nW2 + (size_t)l * DD * DD, DD, nb2 + l * DD, nullptr, nullptr,
            nullptr, nullptr, nullptr, 0, 0, 0, t2, DD, EE);
        gemm_tc<0, false, false, 128><<<dim3(1, GME), 256>>>(
            t2, DD, nW3 + (size_t)l * DD * DD, DD, nb3 + l * DD, nullptr, nullptr,
            nullptr, nullptr, nullptr, 0, 0, 0, nupd, DD, EE);

        // scatter softmax over sink nodes
        zero_buffers<<<(NN * HD + 255) / 256, 256>>>();
        smax_atomic<<<(EE * HH + 255) / 256, 256>>>(snkp);
        att_kernel<<<(EE * HH + 255) / 256, 256>>>(snkp);
        recip_norm<<<(NN * HH + 255) / 256, 256>>>();

        // aggregation
        aggregate<<<(EE * 32 + 255) / 256, 256>>>(snkp);

        // node update + LN + dense MLP + LN
        gemm_tc<0, false, false, 512><<<dim3(1, GMN), 256>>>(
            agg, HD, agW + (size_t)l * HD * DD, DD, agb + l * DD, nullptr, nullptr,
            nullptr, nullptr, nullptr, 0, 0, 0, upd, DD, NN);
        ln_fast<<<(NN + 7) / 8, 256>>>(nodes, upd, n1g + l * DD, n1b + l * DD,
                                       nodes, nullptr, NN);
        gemm_tc<1, false, false, 128><<<dim3(4, GMN), 256>>>(
            nodes, DD, dW1 + (size_t)l * DD * D4, D4, db1 + l * D4, nullptr, nullptr,
            nullptr, nullptr, nullptr, 0, 0, 0, dense, D4, NN);
        gemm_tc<0, false, false, 512><<<dim3(1, GMN), 256>>>(
            dense, D4, dW2 + (size_t)l * D4 * DD, DD, db2 + l * DD, nullptr, nullptr,
            nullptr, nullptr, nullptr, 0, 0, 0, dense2, DD, NN);
        ln_fast<<<(NN + 7) / 8, 256>>>(dense2, upd, n1g + l * DD, n1b + l * DD,
                                       nodes, last ? (float*)d_out : nullptr, NN);

        // per-node partials for emlp1 (new nodes)
        gemm_tc<0, false, false, 128><<<dim3(2, GMN), 256>>>(
            nodes, DD, WU2 + (size_t)l * DD * 256, 256, zerob, nullptr, nullptr,
            nullptr, nullptr, nullptr, 0, 0, 0, U2, 256, NN);

        // edge MLP: W1 (edge part + U2 gathers), W2, W3, LN
        gemm_tc<1, false, true, 128><<<dim3(1, GME), 256>>>(
            eattr, DE, eW1 + ((size_t)l * CC + 256) * DE, DE, eb1 + l * DE,
            nullptr, nullptr, srcp, snkp, U2, 256, 0, 128, t1, DE, EE);
        gemm_tc<1, false, false, 128><<<dim3(1, GME), 256>>>(
            t1, DE, eW2 + (size_t)l * DE * DE, DE, eb2 + l * DE, nullptr, nullptr,
            nullptr, nullptr, nullptr, 0, 0, 0, t2, DE, EE);
        gemm_tc<0, false, false, 128><<<dim3(1, GME), 256>>>(
            t2, DE, eW3 + (size_t)l * DE * DE, DE, eb3 + l * DE, nullptr, nullptr,
            nullptr, nullptr, nullptr, 0, 0, 0, nupd, DE, EE);
        ln_fast<<<(EE + 7) / 8, 256>>>(eattr, nupd, eg + l * DE, eb + l * DE,
                                       eattr, last ? ((float*)d_out + (size_t)NN * DD) : nullptr, EE);
    }
}

// round 10
// speedup vs baseline: 1.2485x; 1.2485x over previous
#include <cuda_runtime.h>
#include <math.h>

#define NN 6000
#define EE 120000
#define DD 128
#define DE 128
#define HH 4
#define LL 2
#define CC 384      // 2*DD + DE
#define HD 512      // HH*DD
#define D4 512      // 4*DD

// ---------------- scratch (device globals; no allocation) ----------------
__device__ float    g_t1[(size_t)EE * DD];
__device__ float    g_t2[(size_t)EE * DD];
__device__ float    g_nupd[(size_t)EE * DD];
__device__ float    g_eattr[(size_t)EE * DE];
__device__ float    g_scores[(size_t)EE * HH];
__device__ float    g_att[(size_t)EE * HH];
__device__ unsigned g_smaxu[NN * HH];
__device__ float    g_norm[NN * HH];
__device__ float    g_agg[(size_t)NN * HD];
__device__ float    g_nodes[NN * DD];
__device__ float    g_upd[NN * DD];
__device__ float    g_dense[(size_t)NN * D4];
__device__ float    g_dense2[NN * DD];
__device__ float    g_Wa[(size_t)LL * CC * HD];    // attention W packed [l][c][h*D+d]
__device__ float    g_WU1[(size_t)LL * DD * 1280]; // [Wa_src|Wa_snk|nW1_src|nW1_snk]
__device__ float    g_WU2[(size_t)LL * DD * 256];  // [eW1_src|eW1_snk]
__device__ float    g_U1[(size_t)NN * 1280];       // per-node partials (attn + nmlp1)
__device__ float    g_U2[(size_t)NN * 256];        // per-node partials (emlp1)
__device__ float    g_zero[1536];                  // zero bias (never written)

// ---------------- helpers ----------------
__device__ __forceinline__ float gelu_f(float x) {
    return 0.5f * x * (1.0f + erff(x * 0.70710678118654752440f));
}
__device__ __forceinline__ unsigned f2u(float f) {
    unsigned u = __float_as_uint(f);
    return (u & 0x80000000u) ? ~u : (u | 0x80000000u);
}
__device__ __forceinline__ float u2f(unsigned u) {
    return (u & 0x80000000u) ? __uint_as_float(u & 0x7fffffffu) : __uint_as_float(~u);
}
__device__ __forceinline__ float tf32f(float x) {
    unsigned r;
    asm("cvt.rna.tf32.f32 %0, %1;" : "=r"(r) : "f"(x));
    return __uint_as_float(r);
}
__device__ __forceinline__ float4 tf32f4(float4 v) {
    return make_float4(tf32f(v.x), tf32f(v.y), tf32f(v.z), tf32f(v.w));
}
__device__ __forceinline__ void mma_tf32(float* d, const unsigned* a, const unsigned* b) {
    asm volatile(
        "mma.sync.aligned.m16n8k8.row.col.f32.tf32.tf32.f32 "
        "{%0,%1,%2,%3}, {%4,%5,%6,%7}, {%8,%9}, {%0,%1,%2,%3};"
        : "+f"(d[0]), "+f"(d[1]), "+f"(d[2]), "+f"(d[3])
        : "r"(a[0]), "r"(a[1]), "r"(a[2]), "r"(a[3]), "r"(b[0]), "r"(b[1]));
}

// ---------------- small kernels ----------------
__global__ void pack_wa(const float* __restrict__ aW) {
    int i = blockIdx.x * blockDim.x + threadIdx.x;
    if (i >= LL * HH * CC * DD) return;
    int d = i % DD;
    int c = (i / DD) % CC;
    int h = (i / (DD * CC)) % HH;
    int l = i / (DD * CC * HH);
    g_Wa[((size_t)l * CC + c) * HD + h * DD + d] = aW[i];
}

__global__ void pack_u1(const float* __restrict__ aW, const float* __restrict__ nW1) {
    int i = blockIdx.x * blockDim.x + threadIdx.x;
    if (i >= LL * DD * 1280) return;
    int j = i % 1280;
    int k = (i / 1280) % DD;
    int l = i / (1280 * DD);
    float v;
    if (j < 1024) {
        int c = (j < 512) ? k : (128 + k);
        int jj = j & 511;
        int h = jj >> 7, d = jj & 127;
        v = aW[(((size_t)l * HH + h) * CC + c) * DD + d];
    } else {
        int c = (j < 1152) ? k : (128 + k);
        int d = (j - 1024) & 127;
        v = nW1[((size_t)l * CC + c) * DD + d];
    }
    g_WU1[i] = v;
}

__global__ void pack_u2(const float* __restrict__ eW1) {
    int i = blockIdx.x * blockDim.x + threadIdx.x;
    if (i >= LL * DD * 256) return;
    int j = i % 256;
    int k = (i / 256) % DD;
    int l = i / (256 * DD);
    int c = (j < 128) ? k : (128 + k);
    g_WU2[i] = eW1[((size_t)l * CC + c) * DE + (j & 127)];
}

__global__ void node_embed(const int* __restrict__ seq, const float* __restrict__ emb) {
    int i = blockIdx.x * blockDim.x + threadIdx.x;
    if (i < NN * DD) g_nodes[i] = emb[seq[i / DD] * DD + (i % DD)];
}

__global__ void edge_init(const float* __restrict__ dist,
                          const float* __restrict__ W, const float* __restrict__ b) {
    int e = blockIdx.x;
    int t = threadIdx.x;
    __shared__ float rbf[16];
    if (t < 16) {
        float mu = 2.0f + (20.0f / 15.0f) * (float)t;
        float z = (dist[e] - mu) * (1.0f / 1.25f);
        rbf[t] = expf(-z * z) + 1e-8f;
    }
    __syncthreads();
    float acc = b[t];
#pragma unroll
    for (int k = 0; k < 16; k++) acc = fmaf(rbf[k], W[k * DE + t], acc);
    g_eattr[(size_t)e * DE + t] = acc;
}

// zero agg + softmax max/norm buffers in one launch
__global__ void zero_buffers() {
    int i = blockIdx.x * blockDim.x + threadIdx.x;
    if (i < NN * HD) g_agg[i] = 0.0f;
    if (i < NN * HH) { g_smaxu[i] = 0u; g_norm[i] = 0.0f; }
}

__global__ void smax_atomic(const int* __restrict__ snk) {
    int i = blockIdx.x * blockDim.x + threadIdx.x;
    if (i >= EE * HH) return;
    int e = i / HH, h = i % HH;
    atomicMax(&g_smaxu[snk[e] * HH + h], f2u(g_scores[i]));
}

__global__ void att_kernel(const int* __restrict__ snk) {
    int i = blockIdx.x * blockDim.x + threadIdx.x;
    if (i >= EE * HH) return;
    int e = i / HH, h = i % HH;
    int s = snk[e];
    float a = expf(g_scores[i] - u2f(g_smaxu[s * HH + h]));
    g_att[i] = a;
    atomicAdd(&g_norm[s * HH + h], a + 1e-12f);
}

__global__ void recip_norm() {
    int i = blockIdx.x * blockDim.x + threadIdx.x;
    if (i < NN * HH) g_norm[i] = 1.0f / g_norm[i];
}

__global__ void aggregate(const int* __restrict__ snk) {
    int i = blockIdx.x * blockDim.x + threadIdx.x;
    if (i >= EE * 32) return;
    int e = i >> 5;
    int d4 = i & 31;
    float4 v = ((const float4*)g_nupd)[(size_t)e * 32 + d4];
    int s = snk[e];
    float4 w = *(const float4*)(g_att + e * 4);
    float4 rn = *(const float4*)(g_norm + s * 4);
    float4* base = (float4*)(g_agg + (size_t)s * HD) + d4;
    float c0 = w.x * rn.x, c1 = w.y * rn.y, c2 = w.z * rn.z, c3 = w.w * rn.w;
    atomicAdd(base,      make_float4(c0 * v.x, c0 * v.y, c0 * v.z, c0 * v.w));
    atomicAdd(base + 32, make_float4(c1 * v.x, c1 * v.y, c1 * v.z, c1 * v.w));
    atomicAdd(base + 64, make_float4(c2 * v.x, c2 * v.y, c2 * v.z, c2 * v.w));
    atomicAdd(base + 96, make_float4(c3 * v.x, c3 * v.y, c3 * v.z, c3 * v.w));
}

// LayerNorm: warp per row, 8 rows per 256-thread block. out = LN(A+R)*g+b.
__global__ void ln_fast(const float* __restrict__ A, const float* __restrict__ R,
                        const float* __restrict__ g, const float* __restrict__ b,
                        float* __restrict__ out, float* __restrict__ out2, int M) {
    int row = blockIdx.x * 8 + (threadIdx.x >> 5);
    if (row >= M) return;
    int lane = threadIdx.x & 31;
    float4 a = *(const float4*)(A + (size_t)row * DD + lane * 4);
    float4 r = *(const float4*)(R + (size_t)row * DD + lane * 4);
    float x0 = a.x + r.x, x1 = a.y + r.y, x2 = a.z + r.z, x3 = a.w + r.w;
    float s = x0 + x1 + x2 + x3;
    float sq = x0 * x0 + x1 * x1 + x2 * x2 + x3 * x3;
#pragma unroll
    for (int o = 16; o > 0; o >>= 1) {
        s  += __shfl_xor_sync(0xffffffffu, s, o);
        sq += __shfl_xor_sync(0xffffffffu, sq, o);
    }
    float mean = s * (1.0f / 128.0f);
    float var = sq * (1.0f / 128.0f) - mean * mean;
    float rstd = rsqrtf(var + 1e-5f);
    float4 gv = *(const float4*)(g + lane * 4);
    float4 bv = *(const float4*)(b + lane * 4);
    float4 o4;
    o4.x = (x0 - mean) * rstd * gv.x + bv.x;
    o4.y = (x1 - mean) * rstd * gv.y + bv.y;
    o4.z = (x2 - mean) * rstd * gv.z + bv.z;
    o4.w = (x3 - mean) * rstd * gv.w + bv.w;
    *(float4*)(out + (size_t)row * DD + lane * 4) = o4;
    if (out2) *(float4*)(out2 + (size_t)row * DD + lane * 4) = o4;
}

// ---------------- tf32 tensor-core GEMM, double-buffered (R5-proven shape) ----------------
// C[M,N] = act(A@B + bias [+ U[src]+U[snk]]). BM=128, BN=128, BK=16, 256 thr,
// warp tile 64x32. N multiple of 128, K runtime (multiple of 16, >= 32).
// ADDUV: epilogue adds U[src[r]*ldu + offS + c] + U[snk[r]*ldu + offK + c].
// ATTN:  BN==head width; lrelu then dot(aA) reduced to g_scores directly.
template <int ACT, bool ATTN, bool ADDUV>   // ACT: 0 none, 1 gelu
__global__ void __launch_bounds__(256) gemm_tc(
    const float* __restrict__ A, int lda,
    const float* __restrict__ B, int ldb,
    const float* __restrict__ bias,
    const float* __restrict__ aA, const float* __restrict__ aAb,
    const int* __restrict__ srcI, const int* __restrict__ snkI,
    const float* __restrict__ U, int ldu, int offS, int offK,
    float* __restrict__ C, int ldc, int M, int K) {
    __shared__ float As[2][128][20];
    __shared__ float Bs[2][16][136];
    __shared__ float sred[128][5];
    const int tid = threadIdx.x;
    const int row0 = blockIdx.y * 128, col0 = blockIdx.x * 128;
    const int wid = tid >> 5, lane = tid & 31, g = lane >> 2, tig = lane & 3;
    const int wm0 = (wid >> 2) * 64, wn0 = (wid & 3) * 32;

    const int arow = tid >> 2, acol = (tid & 3) * 4;
    const int ag0 = min(row0 + arow, M - 1);
    const int ag1 = min(row0 + arow + 64, M - 1);
    const int brow = tid >> 5, bcol = (tid & 31) * 4;

    const float* Ap0 = A + (size_t)ag0 * lda + acol;
    const float* Ap1 = A + (size_t)ag1 * lda + acol;
    const float* Bp  = B + (size_t)brow * ldb + col0 + bcol;

    float4 ar0 = *(const float4*)Ap0;
    float4 ar1 = *(const float4*)Ap1;
    float4 br0 = *(const float4*)Bp;
    float4 br1 = *(const float4*)(Bp + (size_t)8 * ldb);
    *(float4*)&As[0][arow][acol]      = tf32f4(ar0);
    *(float4*)&As[0][arow + 64][acol] = tf32f4(ar1);
    *(float4*)&Bs[0][brow][bcol]      = tf32f4(br0);
    *(float4*)&Bs[0][brow + 8][bcol]  = tf32f4(br1);
    __syncthreads();

    float acc[4][4][4] = {};
    int buf = 0;
    for (int k0 = 0; k0 < K; k0 += 16, buf ^= 1) {
        const bool more = (k0 + 16) < K;
        if (more) {
            ar0 = *(const float4*)(Ap0 + k0 + 16);
            ar1 = *(const float4*)(Ap1 + k0 + 16);
            br0 = *(const float4*)(Bp + (size_t)(k0 + 16) * ldb);
            br1 = *(const float4*)(Bp + (size_t)(k0 + 24) * ldb);
        }
#pragma unroll
        for (int ks = 0; ks < 16; ks += 8) {
            unsigned af[4][4], bf[4][2];
#pragma unroll
            for (int mt = 0; mt < 4; mt++) {
                int r = wm0 + mt * 16 + g;
                af[mt][0] = __float_as_uint(As[buf][r][ks + tig]);
                af[mt][1] = __float_as_uint(As[buf][r + 8][ks + tig]);
                af[mt][2] = __float_as_uint(As[buf][r][ks + tig + 4]);
                af[mt][3] = __float_as_uint(As[buf][r + 8][ks + tig + 4]);
            }
#pragma unroll
            for (int nt = 0; nt < 4; nt++) {
                int c = wn0 + nt * 8 + g;
                bf[nt][0] = __float_as_uint(Bs[buf][ks + tig][c]);
                bf[nt][1] = __float_as_uint(Bs[buf][ks + tig + 4][c]);
            }
#pragma unroll
            for (int mt = 0; mt < 4; mt++)
#pragma unroll
                for (int nt = 0; nt < 4; nt++)
                    mma_tf32(acc[mt][nt], af[mt], bf[nt]);
        }
        if (more) {
            *(float4*)&As[buf ^ 1][arow][acol]      = tf32f4(ar0);
            *(float4*)&As[buf ^ 1][arow + 64][acol] = tf32f4(ar1);
            *(float4*)&Bs[buf ^ 1][brow][bcol]      = tf32f4(br0);
            *(float4*)&Bs[buf ^ 1][brow + 8][bcol]  = tf32f4(br1);
        }
        __syncthreads();
    }

#pragma unroll
    for (int mt = 0; mt < 4; mt++) {
#pragma unroll
        for (int i2 = 0; i2 < 2; i2++) {
            int rl = wm0 + mt * 16 + i2 * 8 + g;
            int gr = row0 + rl;
            int grc = min(gr, M - 1);
            int sI = 0, kI = 0;
            if (ADDUV) { sI = srcI[grc]; kI = snkI[grc]; }
            float p = 0.0f;
#pragma unroll
            for (int nt = 0; nt < 4; nt++) {
                int gc = col0 + wn0 + nt * 8 + 2 * tig;
                float2 bb = *(const float2*)&bias[gc];
                float v0 = acc[mt][nt][i2 * 2 + 0] + bb.x;
                float v1 = acc[mt][nt][i2 * 2 + 1] + bb.y;
                if (ADDUV) {
                    float2 us = *(const float2*)&U[(size_t)sI * ldu + offS + gc];
                    float2 uk = *(const float2*)&U[(size_t)kI * ldu + offK + gc];
                    v0 += us.x + uk.x;
                    v1 += us.y + uk.y;
                }
                if (ATTN) {
                    v0 = (v0 > 0.0f) ? v0 : 0.2f * v0;
                    v1 = (v1 > 0.0f) ? v1 : 0.2f * v1;
                    float2 a2 = *(const float2*)&aA[gc];
                    p = fmaf(v0, a2.x, p);
                    p = fmaf(v1, a2.y, p);
                } else {
                    if (ACT == 1) { v0 = gelu_f(v0); v1 = gelu_f(v1); }
                    if (gr < M) *(float2*)&C[(size_t)gr * ldc + gc] = make_float2(v0, v1);
                }
            }
            if (ATTN) {
                p += __shfl_xor_sync(0xffffffffu, p, 1);
                p += __shfl_xor_sync(0xffffffffu, p, 2);
                if (tig == 0) sred[rl][wid & 3] = p;
            }
        }
    }
    if (ATTN) {
        __syncthreads();
        if (tid < 128) {
            int gr = row0 + tid;
            if (gr < M) {
                int head = col0 >> 7;
                g_scores[gr * HH + head] =
                    sred[tid][0] + sred[tid][1] + sred[tid][2] + sred[tid][3] + aAb[head];
            }
        }
    }
}

// ---------------- host ----------------
static inline void* sym(const void* s) {
    void* p = nullptr;
    cudaGetSymbolAddress(&p, s);
    return p;
}

extern "C" void kernel_launch(void* const* d_in, const int* in_sizes, int n_in,
                              void* d_out, int out_size) {
    const int*   seq      = (const int*)d_in[0];
    const int*   eidx     = (const int*)d_in[1];
    const float* dist     = (const float*)d_in[2];
    const float* seq_emb  = (const float*)d_in[3];
    const float* elW      = (const float*)d_in[4];
    const float* elb      = (const float*)d_in[5];
    const float* aW_W     = (const float*)d_in[6];
    const float* aW_b     = (const float*)d_in[7];
    const float* aA_W     = (const float*)d_in[8];
    const float* aA_b     = (const float*)d_in[9];
    const float* nW1 = (const float*)d_in[10]; const float* nb1 = (const float*)d_in[11];
    const float* nW2 = (const float*)d_in[12]; const float* nb2 = (const float*)d_in[13];
    const float* nW3 = (const float*)d_in[14]; const float* nb3 = (const float*)d_in[15];
    const float* dW1 = (const float*)d_in[16]; const float* db1 = (const float*)d_in[17];
    const float* dW2 = (const float*)d_in[18]; const float* db2 = (const float*)d_in[19];
    const float* eW1 = (const float*)d_in[20]; const float* eb1 = (const float*)d_in[21];
    const float* eW2 = (const float*)d_in[22]; const float* eb2 = (const float*)d_in[23];
    const float* eW3 = (const float*)d_in[24]; const float* eb3 = (const float*)d_in[25];
    const float* agW = (const float*)d_in[26]; const float* agb = (const float*)d_in[27];
    const float* n1g = (const float*)d_in[28]; const float* n1b = (const float*)d_in[29];
    const float* eg  = (const float*)d_in[30]; const float* eb  = (const float*)d_in[31];

    const int* srcp = eidx;
    const int* snkp = eidx + EE;

    float* t1     = (float*)sym(g_t1);
    float* t2     = (float*)sym(g_t2);
    float* nupd   = (float*)sym(g_nupd);
    float* agg    = (float*)sym(g_agg);
    float* nodes  = (float*)sym(g_nodes);
    float* upd    = (float*)sym(g_upd);
    float* dense  = (float*)sym(g_dense);
    float* dense2 = (float*)sym(g_dense2);
    float* Wa     = (float*)sym(g_Wa);
    float* WU1    = (float*)sym(g_WU1);
    float* WU2    = (float*)sym(g_WU2);
    float* U1     = (float*)sym(g_U1);
    float* U2     = (float*)sym(g_U2);
    float* zerob  = (float*)sym(g_zero);
    float* eattr  = (float*)sym(g_eattr);

    const int GME = (EE + 127) / 128;
    const int GMN = (NN + 127) / 128;

    {
        pack_wa<<<(LL * HH * CC * DD + 255) / 256, 256>>>(aW_W);
        pack_u1<<<(LL * DD * 1280 + 255) / 256, 256>>>(aW_W, nW1);
        pack_u2<<<(LL * DD * 256 + 255) / 256, 256>>>(eW1);
        node_embed<<<(NN * DD + 255) / 256, 256>>>(seq, seq_emb);
        edge_init<<<EE, 128>>>(dist, elW, elb);
    }

    for (int l = 0; l < LL; l++) {
        const bool last = (l == LL - 1);

        // per-node partials for attn + nmlp1
        gemm_tc<0, false, false><<<dim3(10, GMN), 256>>>(
            nodes, DD, WU1 + (size_t)l * DD * 1280, 1280, zerob, nullptr, nullptr,
            nullptr, nullptr, nullptr, 0, 0, 0, U1, 1280, NN, DD);

        // attention scores: eattr @ Wa_e + U1 gathers, lrelu, dot(aA)
        gemm_tc<0, true, true><<<dim3(4, GME), 256>>>(
            eattr, DE, Wa + ((size_t)l * CC + 256) * HD, HD, aW_b + l * HD,
            aA_W + l * HD, aA_b + l * HH,
            srcp, snkp, U1, 1280, 0, 512, nullptr, 0, EE, DD);

        // nmlp: W1 (edge part + U1 gathers), then W2, W3
        gemm_tc<1, false, true><<<dim3(1, GME), 256>>>(
            eattr, DE, nW1 + ((size_t)l * CC + 256) * DD, DD, nb1 + l * DD,
            nullptr, nullptr, srcp, snkp, U1, 1280, 1024, 1152, t1, DD, EE, DD);
        gemm_tc<1, false, false><<<dim3(1, GME), 256>>>(
            t1, DD, nW2 + (size_t)l * DD * DD, DD, nb2 + l * DD, nullptr, nullptr,
            nullptr, nullptr, nullptr, 0, 0, 0, t2, DD, EE, DD);
        gemm_tc<0, false, false><<<dim3(1, GME), 256>>>(
            t2, DD, nW3 + (size_t)l * DD * DD, DD, nb3 + l * DD, nullptr, nullptr,
            nullptr, nullptr, nullptr, 0, 0, 0, nupd, DD, EE, DD);

        // scatter softmax over sink nodes
        zero_buffers<<<(NN * HD + 255) / 256, 256>>>();
        smax_atomic<<<(EE * HH + 255) / 256, 256>>>(snkp);
        att_kernel<<<(EE * HH + 255) / 256, 256>>>(snkp);
        recip_norm<<<(NN * HH + 255) / 256, 256>>>();

        // aggregation
        aggregate<<<(EE * 32 + 255) / 256, 256>>>(snkp);

        // node update + LN + dense MLP + LN
        gemm_tc<0, false, false><<<dim3(1, GMN), 256>>>(
            agg, HD, agW + (size_t)l * HD * DD, DD, agb + l * DD, nullptr, nullptr,
            nullptr, nullptr, nullptr, 0, 0, 0, upd, DD, NN, HD);
        ln_fast<<<(NN + 7) / 8, 256>>>(nodes, upd, n1g + l * DD, n1b + l * DD,
                                       nodes, nullptr, NN);
        gemm_tc<1, false, false><<<dim3(4, GMN), 256>>>(
            nodes, DD, dW1 + (size_t)l * DD * D4, D4, db1 + l * D4, nullptr, nullptr,
            nullptr, nullptr, nullptr, 0, 0, 0, dense, D4, NN, DD);
        gemm_tc<0, false, false><<<dim3(1, GMN), 256>>>(
            dense, D4, dW2 + (size_t)l * D4 * DD, DD, db2 + l * DD, nullptr, nullptr,
            nullptr, nullptr, nullptr, 0, 0, 0, dense2, DD, NN, D4);
        ln_fast<<<(NN + 7) / 8, 256>>>(dense2, upd, n1g + l * DD, n1b + l * DD,
                                       nodes, last ? (float*)d_out : nullptr, NN);

        // per-node partials for emlp1 (new nodes)
        gemm_tc<0, false, false><<<dim3(2, GMN), 256>>>(
            nodes, DD, WU2 + (size_t)l * DD * 256, 256, zerob, nullptr, nullptr,
            nullptr, nullptr, nullptr, 0, 0, 0, U2, 256, NN, DD);

        // edge MLP: W1 (edge part + U2 gathers), W2, W3, LN
        gemm_tc<1, false, true><<<dim3(1, GME), 256>>>(
            eattr, DE, eW1 + ((size_t)l * CC + 256) * DE, DE, eb1 + l * DE,
            nullptr, nullptr, srcp, snkp, U2, 256, 0, 128, t1, DE, EE, DD);
        gemm_tc<1, false, false><<<dim3(1, GME), 256>>>(
            t1, DE, eW2 + (size_t)l * DE * DE, DE, eb2 + l * DE, nullptr, nullptr,
            nullptr, nullptr, nullptr, 0, 0, 0, t2, DE, EE, DE);
        gemm_tc<0, false, false><<<dim3(1, GME), 256>>>(
            t2, DE, eW3 + (size_t)l * DE * DE, DE, eb3 + l * DE, nullptr, nullptr,
            nullptr, nullptr, nullptr, 0, 0, 0, nupd, DE, EE, DE);
        ln_fast<<<(EE + 7) / 8, 256>>>(eattr, nupd, eg + l * DE, eb + l * DE,
                                       eattr, last ? ((float*)d_out + (size_t)NN * DD) : nullptr, EE);
    }
}